// round 12
// baseline (speedup 1.0000x reference)
#include <cuda_runtime.h>
#include <cuda_bf16.h>
#include <cuda_fp16.h>
#include <math_constants.h>
#include <cstdint>

// Problem constants
#define BATCH 4
#define CDIM 256
#define NTOK 4096          // 64*64
#define HEADS 4
#define DH 32
#define HID 128            // HEADS*DH
#define OQKV 384           // 3*HID
#define NPB 1048576        // CDIM*NTOK per batch
#define SCALE_LOG2E 0.25494291280534f  // 32^-0.5 * log2(e)

// ---------------- device scratch ----------------
__device__ float g_psum[BATCH * 64];
__device__ float g_psq [BATCH * 64];
__device__ float g_mu[BATCH];
__device__ float g_rs[BATCH];
__device__ __half g_qh[BATCH * HEADS * NTOK * DH];   // pre-scaled by SCALE*log2e
__device__ __half g_kh[BATCH * HEADS * NTOK * DH];
__device__ __half g_vh[BATCH * HEADS * NTOK * DH];
__device__ float g_ao[BATCH * HID * NTOK];           // [b][c][i]

__device__ __forceinline__ uint32_t smem_u32(const void* p) {
    uint32_t a;
    asm("{ .reg .u64 t; cvta.to.shared.u64 t, %1; cvt.u32.u64 %0, t; }" : "=r"(a) : "l"(p));
    return a;
}
__device__ __forceinline__ void ldsm_x4(uint32_t* r, uint32_t a) {
    asm volatile("ldmatrix.sync.aligned.m8n8.x4.shared.b16 {%0,%1,%2,%3}, [%4];"
                 : "=r"(r[0]), "=r"(r[1]), "=r"(r[2]), "=r"(r[3]) : "r"(a));
}
__device__ __forceinline__ void ldsm_x4_t(uint32_t* r, uint32_t a) {
    asm volatile("ldmatrix.sync.aligned.m8n8.x4.trans.shared.b16 {%0,%1,%2,%3}, [%4];"
                 : "=r"(r[0]), "=r"(r[1]), "=r"(r[2]), "=r"(r[3]) : "r"(a));
}
#define MMA_BF16(d, a, b0_, b1_) \
    asm volatile("mma.sync.aligned.m16n8k16.row.col.f32.bf16.bf16.f32 " \
                 "{%0,%1,%2,%3}, {%4,%5,%6,%7}, {%8,%9}, {%0,%1,%2,%3};" \
                 : "+f"((d)[0]), "+f"((d)[1]), "+f"((d)[2]), "+f"((d)[3]) \
                 : "r"((a)[0]), "r"((a)[1]), "r"((a)[2]), "r"((a)[3]), "r"(b0_), "r"(b1_))
#define MMA_F16(d, a, b0_, b1_) \
    asm volatile("mma.sync.aligned.m16n8k16.row.col.f32.f16.f16.f32 " \
                 "{%0,%1,%2,%3}, {%4,%5,%6,%7}, {%8,%9}, {%0,%1,%2,%3};" \
                 : "+f"((d)[0]), "+f"((d)[1]), "+f"((d)[2]), "+f"((d)[3]) \
                 : "r"((a)[0]), "r"((a)[1]), "r"((a)[2]), "r"((a)[3]), "r"(b0_), "r"(b1_))
#define PACK_BF16X2(r, lo, hi) \
    asm("cvt.rn.bf16x2.f32 %0, %1, %2;" : "=r"(r) : "f"(hi), "f"(lo))
#define PACK_F16X2(r, lo, hi) \
    asm("cvt.rn.f16x2.f32 %0, %1, %2;" : "=r"(r) : "f"(hi), "f"(lo))
#define EX2_F16X2(r, a) \
    asm("ex2.approx.f16x2 %0, %1;" : "=r"(r) : "r"(a))
#define ONES_F16X2 0x3C003C00u

// exact truncation split: f = hi(bf16, trunc) + lo residual (for fp32-accurate GEMM)
__device__ __forceinline__ void split_pack2(uint32_t& h, uint32_t& l, float a, float b) {
    uint32_t ua = __float_as_uint(a), ub = __float_as_uint(b);
    h = (ua >> 16) | (ub & 0xffff0000u);
    float la = a - __uint_as_float(ua & 0xffff0000u);
    float lb = b - __uint_as_float(ub & 0xffff0000u);
    PACK_BF16X2(l, la, lb);
}
__device__ __forceinline__ void split8_store(__nv_bfloat16* dh, __nv_bfloat16* dl,
                                             float4 a, float4 b) {
    uint4 H, L;
    split_pack2(H.x, L.x, a.x, a.y);
    split_pack2(H.y, L.y, a.z, a.w);
    split_pack2(H.z, L.z, b.x, b.y);
    split_pack2(H.w, L.w, b.z, b.w);
    *(uint4*)dh = H;
    *(uint4*)dl = L;
}

// ---------------- kernel 1: per-batch sum / sumsq partials ----------------
__global__ void k_reduce1(const float* __restrict__ x) {
    int b = blockIdx.y;
    int blk = blockIdx.x;
    int tid = threadIdx.x;
    const float4* xb = (const float4*)(x + (size_t)b * NPB);
    float s = 0.f, sq = 0.f;
    int base = blk * 4096 + tid;
    #pragma unroll
    for (int t = 0; t < 16; t++) {
        float4 v = xb[base + t * 256];
        s  += (v.x + v.y) + (v.z + v.w);
        sq += (v.x * v.x + v.y * v.y) + (v.z * v.z + v.w * v.w);
    }
    __shared__ float ss[256], sg[256];
    ss[tid] = s; sg[tid] = sq;
    __syncthreads();
    for (int off = 128; off >= 1; off >>= 1) {
        if (tid < off) { ss[tid] += ss[tid + off]; sg[tid] += sg[tid + off]; }
        __syncthreads();
    }
    if (tid == 0) { g_psum[b * 64 + blk] = ss[0]; g_psq[b * 64 + blk] = sg[0]; }
}

// ---------------- kernel 2: finalize mean / rsigma ----------------
__global__ void k_reduce2() {
    int tid = threadIdx.x;
    int b = tid / 64, j = tid % 64;
    __shared__ float ss[256], sg[256];
    ss[tid] = g_psum[tid]; sg[tid] = g_psq[tid];
    __syncthreads();
    for (int off = 32; off >= 1; off >>= 1) {
        if (j < off) { ss[tid] += ss[tid + off]; sg[tid] += sg[tid + off]; }
        __syncthreads();
    }
    if (j == 0) {
        float mu = ss[tid] * (1.f / (float)NPB);
        float var = sg[tid] * (1.f / (float)NPB) - mu * mu;
        g_mu[b] = mu;
        g_rs[b] = rsqrtf(var + 1e-5f);
    }
}

// ---------------- kernel 3: LN + QKV GEMM (split-bf16 tensor cores) --------
__global__ void __launch_bounds__(256) k_qkv_mma(const float* __restrict__ x,
                                                 const float* __restrict__ gamma,
                                                 const float* __restrict__ beta,
                                                 const float* __restrict__ wqkv) {
    __shared__ __align__(16) __nv_bfloat16 Ash[2][128][24];
    __shared__ __align__(16) __nv_bfloat16 Asl[2][128][24];
    __shared__ __align__(16) __nv_bfloat16 Bsh[2][16][136];
    __shared__ __align__(16) __nv_bfloat16 Bsl[2][16][136];

    int b = blockIdx.z;
    int i0 = blockIdx.x * 128;
    int which = blockIdx.y;            // 0=q, 1=k, 2=v
    int obase = which * 128;
    int tid = threadIdx.x;
    int wid = tid >> 5, lane = tid & 31;
    int wm = (wid >> 2) * 64;
    int wn = (wid & 3) * 32;
    int lr = lane & 7, lm = lane >> 3;

    float mu = g_mu[b], rs = g_rs[b];
    const float* xb = x + (size_t)b * NPB;

    int arow = tid >> 1, ac = (tid & 1) * 8;
    int brow = tid >> 4, bi = (tid & 15) * 8;

    float4 wa0, wa1, xa0, xa1;
    {
        const float* wr = wqkv + (size_t)(obase + arow) * CDIM + ac;
        wa0 = *(const float4*)(wr);
        wa1 = *(const float4*)(wr + 4);
        const float* xr = xb + (size_t)brow * NTOK + i0 + bi;
        xa0 = *(const float4*)(xr);
        xa1 = *(const float4*)(xr + 4);
    }
    {
        split8_store(&Ash[0][arow][ac], &Asl[0][arow][ac], wa0, wa1);
        float a = rs * __ldg(&gamma[brow]);
        float bb = __ldg(&beta[brow]) - mu * a;
        float4 t0 = make_float4(xa0.x*a+bb, xa0.y*a+bb, xa0.z*a+bb, xa0.w*a+bb);
        float4 t1 = make_float4(xa1.x*a+bb, xa1.y*a+bb, xa1.z*a+bb, xa1.w*a+bb);
        split8_store(&Bsh[0][brow][bi], &Bsl[0][brow][bi], t0, t1);
    }
    __syncthreads();

    float acc[4][4][4] = {};
    #pragma unroll 1
    for (int kt = 0; kt < 16; kt++) {
        int buf = kt & 1;
        if (kt < 15) {
            int k0 = (kt + 1) * 16;
            const float* wr = wqkv + (size_t)(obase + arow) * CDIM + k0 + ac;
            wa0 = *(const float4*)(wr);
            wa1 = *(const float4*)(wr + 4);
            const float* xr = xb + (size_t)(k0 + brow) * NTOK + i0 + bi;
            xa0 = *(const float4*)(xr);
            xa1 = *(const float4*)(xr + 4);
        }
        uint32_t ah[4][4], al[4][4];
        #pragma unroll
        for (int mt = 0; mt < 4; mt++) {
            int r = wm + mt * 16 + (lm & 1) * 8 + lr;
            ldsm_x4(ah[mt], smem_u32(&Ash[buf][r][(lm >> 1) * 8]));
            ldsm_x4(al[mt], smem_u32(&Asl[buf][r][(lm >> 1) * 8]));
        }
        uint32_t bh[2][4], bl[2][4];
        #pragma unroll
        for (int np = 0; np < 2; np++) {
            int r = (lm & 1) * 8 + lr;
            int c = wn + np * 16 + (lm >> 1) * 8;
            ldsm_x4_t(bh[np], smem_u32(&Bsh[buf][r][c]));
            ldsm_x4_t(bl[np], smem_u32(&Bsl[buf][r][c]));
        }
        #pragma unroll
        for (int mt = 0; mt < 4; mt++)
            #pragma unroll
            for (int nt = 0; nt < 4; nt++) {
                int np = nt >> 1, pp = (nt & 1) * 2;
                MMA_BF16(acc[mt][nt], ah[mt], bh[np][pp], bh[np][pp + 1]);
                MMA_BF16(acc[mt][nt], al[mt], bh[np][pp], bh[np][pp + 1]);
                MMA_BF16(acc[mt][nt], ah[mt], bl[np][pp], bl[np][pp + 1]);
            }
        if (kt < 15) {
            int k0 = (kt + 1) * 16;
            split8_store(&Ash[buf ^ 1][arow][ac], &Asl[buf ^ 1][arow][ac], wa0, wa1);
            int c = k0 + brow;
            float a = rs * __ldg(&gamma[c]);
            float bb = __ldg(&beta[c]) - mu * a;
            float4 t0 = make_float4(xa0.x*a+bb, xa0.y*a+bb, xa0.z*a+bb, xa0.w*a+bb);
            float4 t1 = make_float4(xa1.x*a+bb, xa1.y*a+bb, xa1.z*a+bb, xa1.w*a+bb);
            split8_store(&Bsh[buf ^ 1][brow][bi], &Bsl[buf ^ 1][brow][bi], t0, t1);
        }
        __syncthreads();
    }

    // epilogue: scatter to q / k / v (fp16)
    #pragma unroll
    for (int mt = 0; mt < 4; mt++) {
        #pragma unroll
        for (int rr = 0; rr < 2; rr++) {
            int ol = wm + mt * 16 + (lane >> 2) + rr * 8;
            int head = ol >> 5, d = ol & 31;
            size_t base = ((size_t)(b * HEADS + head) * NTOK) * DH + d;
            #pragma unroll
            for (int nt = 0; nt < 4; nt++) {
                int i = i0 + wn + nt * 8 + (lane & 3) * 2;
                float v0 = acc[mt][nt][rr * 2];
                float v1 = acc[mt][nt][rr * 2 + 1];
                size_t idx0 = base + (size_t)i * DH;
                size_t idx1 = base + (size_t)(i + 1) * DH;
                if (which == 0) {
                    g_qh[idx0] = __float2half_rn(v0 * SCALE_LOG2E);
                    g_qh[idx1] = __float2half_rn(v1 * SCALE_LOG2E);
                } else if (which == 1) {
                    g_kh[idx0] = __float2half_rn(v0);
                    g_kh[idx1] = __float2half_rn(v1);
                } else {
                    g_vh[idx0] = __float2half_rn(v0);
                    g_vh[idx1] = __float2half_rn(v1);
                }
            }
        }
    }
}

// ---------------- kernel 4: flash attention ---------------------------------
// 128 threads / 4 warps, 32 q-rows per warp (m-tiles=2). 16-key granularity
// end-to-end: QK MMAs for 16 keys -> ex2.f16x2 -> PV + ones MMA, so scores
// never occupy more than 16 regs -> <=128 regs -> 4 CTAs/SM -> single wave.
// grid: (32 q-tiles, 16 bh). Q staged through the K-buffer overlay.
__global__ void __launch_bounds__(128, 4) k_attn_mma() {
    __shared__ __align__(16) __half Ks[2][64][40];
    __shared__ __align__(16) __half Vs[2][64][40];

    int tid = threadIdx.x;
    int wid = tid >> 5, lane = tid & 31;
    int bh = blockIdx.y;
    int i0 = blockIdx.x * 128;
    int wrow = wid * 32;

    const __half* kb = g_kh + (size_t)bh * NTOK * DH;
    const __half* vb = g_vh + (size_t)bh * NTOK * DH;
    const __half* qg = g_qh + (size_t)bh * NTOK * DH;

    // stage Q (128 x 32 fp16 = 10KB) over the whole Ks region (2*64 rows)
    __half (*Qs)[40] = &Ks[0][0];
    {
        int qr = tid;   // 128 rows, 1 row per thread
        const __half* src = qg + (size_t)(i0 + qr) * DH;
        *(uint4*)&Qs[qr][0]  = *(const uint4*)(src);
        *(uint4*)&Qs[qr][8]  = *(const uint4*)(src + 8);
        *(uint4*)&Qs[qr][16] = *(const uint4*)(src + 16);
        *(uint4*)&Qs[qr][24] = *(const uint4*)(src + 24);
    }
    __syncthreads();

    int lr = lane & 7, lm = lane >> 3;

    // Q fragments: A m16k16 per (mt, ks)
    uint32_t qf[2][2][4];
    #pragma unroll
    for (int mt = 0; mt < 2; mt++)
        #pragma unroll
        for (int ks = 0; ks < 2; ks++)
            ldsm_x4(qf[mt][ks],
                    smem_u32(&Qs[wrow + mt * 16 + (lm & 1) * 8 + lr][ks * 16 + (lm >> 1) * 8]));
    __syncthreads();   // done reading Q before K tile 0 overwrites

    float o[2][4][4] = {};
    float lacc[2][4] = {};   // ones-column accumulators (row sums of P)

    // prefetch: tile = 64 rows x 64B per matrix = 256 x 16B chunks; 2/thread
    int c0 = tid, c1 = tid + 128;
    int r0 = c0 >> 2, ch0 = (c0 & 3) * 8;
    int r1 = c1 >> 2, ch1 = (c1 & 3) * 8;

    uint4 kp0 = *(const uint4*)(kb + (size_t)r0 * DH + ch0);
    uint4 kp1 = *(const uint4*)(kb + (size_t)r1 * DH + ch1);
    uint4 vp0 = *(const uint4*)(vb + (size_t)r0 * DH + ch0);
    uint4 vp1 = *(const uint4*)(vb + (size_t)r1 * DH + ch1);
    *(uint4*)&Ks[0][r0][ch0] = kp0;
    *(uint4*)&Ks[0][r1][ch1] = kp1;
    *(uint4*)&Vs[0][r0][ch0] = vp0;
    *(uint4*)&Vs[0][r1][ch1] = vp1;
    __syncthreads();

    #pragma unroll 1
    for (int t = 0; t < NTOK / 64; t++) {
        int buf = t & 1;
        if (t < NTOK / 64 - 1) {
            size_t j0 = (size_t)(t + 1) * 64;
            kp0 = *(const uint4*)(kb + (j0 + r0) * DH + ch0);
            kp1 = *(const uint4*)(kb + (j0 + r1) * DH + ch1);
            vp0 = *(const uint4*)(vb + (j0 + r0) * DH + ch0);
            vp1 = *(const uint4*)(vb + (j0 + r1) * DH + ch1);
        }

        // ---- per 16-key chunk: QK MMAs -> ex2 -> PV + ones MMA ----
        #pragma unroll
        for (int kk = 0; kk < 4; kk++) {
            // S chunk = Q @ K[kk*16 .. kk*16+15]^T
            uint32_t kf0[4], kf1[4];
            ldsm_x4(kf0, smem_u32(&Ks[buf][kk * 16 + (lm >> 1) * 8 + lr][(lm & 1) * 8]));
            ldsm_x4(kf1, smem_u32(&Ks[buf][kk * 16 + (lm >> 1) * 8 + lr][16 + (lm & 1) * 8]));
            float s[2][2][4] = {};
            #pragma unroll
            for (int mt = 0; mt < 2; mt++) {
                MMA_F16(s[mt][0], qf[mt][0], kf0[0], kf0[1]);
                MMA_F16(s[mt][1], qf[mt][0], kf0[2], kf0[3]);
                MMA_F16(s[mt][0], qf[mt][1], kf1[0], kf1[1]);
                MMA_F16(s[mt][1], qf[mt][1], kf1[2], kf1[3]);
            }

            uint32_t vf[2][4];
            #pragma unroll
            for (int dp = 0; dp < 2; dp++)
                ldsm_x4_t(vf[dp],
                          smem_u32(&Vs[buf][kk * 16 + (lm & 1) * 8 + lr][dp * 16 + (lm >> 1) * 8]));
            #pragma unroll
            for (int mt = 0; mt < 2; mt++) {
                uint32_t af[4];
                PACK_F16X2(af[0], s[mt][0][0], s[mt][0][1]);
                PACK_F16X2(af[1], s[mt][0][2], s[mt][0][3]);
                PACK_F16X2(af[2], s[mt][1][0], s[mt][1][1]);
                PACK_F16X2(af[3], s[mt][1][2], s[mt][1][3]);
                EX2_F16X2(af[0], af[0]);
                EX2_F16X2(af[1], af[1]);
                EX2_F16X2(af[2], af[2]);
                EX2_F16X2(af[3], af[3]);
                MMA_F16(o[mt][0], af, vf[0][0], vf[0][1]);
                MMA_F16(o[mt][1], af, vf[0][2], vf[0][3]);
                MMA_F16(o[mt][2], af, vf[1][0], vf[1][1]);
                MMA_F16(o[mt][3], af, vf[1][2], vf[1][3]);
                MMA_F16(lacc[mt], af, ONES_F16X2, ONES_F16X2);
            }
        }

        if (t < NTOK / 64 - 1) {
            *(uint4*)&Ks[buf ^ 1][r0][ch0] = kp0;
            *(uint4*)&Ks[buf ^ 1][r1][ch1] = kp1;
            *(uint4*)&Vs[buf ^ 1][r0][ch0] = vp0;
            *(uint4*)&Vs[buf ^ 1][r1][ch1] = vp1;
        }
        __syncthreads();
    }

    // ---- epilogue (each thread owns its rows' sums; no shfl) ----
    int b = bh >> 2, hd = bh & 3;
    float* dst = g_ao + ((size_t)b * HID + hd * DH) * NTOK;
    int cbase = (lane & 3) * 2;
    #pragma unroll
    for (int mt = 0; mt < 2; mt++) {
        int rbase = i0 + wrow + mt * 16 + (lane >> 2);
        #pragma unroll
        for (int h = 0; h < 2; h++) {
            int i = rbase + h * 8;
            float inv = 1.f / lacc[mt][h * 2];
            #pragma unroll
            for (int dd = 0; dd < 4; dd++) {
                int d = dd * 8 + cbase;
                dst[(size_t)d * NTOK + i]       = o[mt][dd][h * 2]     * inv;
                dst[(size_t)(d + 1) * NTOK + i] = o[mt][dd][h * 2 + 1] * inv;
            }
        }
    }
}

// ---------------- kernel 5: output GEMM + bias (split-bf16 tensor cores) ----
__global__ void __launch_bounds__(256) k_out_mma(float* __restrict__ y,
                                                 const float* __restrict__ wout,
                                                 const float* __restrict__ b_out) {
    __shared__ __align__(16) __nv_bfloat16 Ash[2][128][24];
    __shared__ __align__(16) __nv_bfloat16 Asl[2][128][24];
    __shared__ __align__(16) __nv_bfloat16 Bsh[2][16][136];
    __shared__ __align__(16) __nv_bfloat16 Bsl[2][16][136];

    int b = blockIdx.z;
    int i0 = blockIdx.x * 128;
    int obase = blockIdx.y * 128;
    int tid = threadIdx.x;
    int wid = tid >> 5, lane = tid & 31;
    int wm = (wid >> 2) * 64;
    int wn = (wid & 3) * 32;
    int lr = lane & 7, lm = lane >> 3;

    const float* ab = g_ao + (size_t)b * HID * NTOK;

    int arow = tid >> 1, ac = (tid & 1) * 8;
    int brow = tid >> 4, bi = (tid & 15) * 8;

    float4 wa0, wa1, xa0, xa1;
    {
        const float* wr = wout + (size_t)(obase + arow) * HID + ac;
        wa0 = *(const float4*)(wr);
        wa1 = *(const float4*)(wr + 4);
        const float* xr = ab + (size_t)brow * NTOK + i0 + bi;
        xa0 = *(const float4*)(xr);
        xa1 = *(const float4*)(xr + 4);
    }
    split8_store(&Ash[0][arow][ac], &Asl[0][arow][ac], wa0, wa1);
    split8_store(&Bsh[0][brow][bi], &Bsl[0][brow][bi], xa0, xa1);
    __syncthreads();

    float acc[4][4][4] = {};
    #pragma unroll 1
    for (int kt = 0; kt < 8; kt++) {
        int buf = kt & 1;
        if (kt < 7) {
            int k0 = (kt + 1) * 16;
            const float* wr = wout + (size_t)(obase + arow) * HID + k0 + ac;
            wa0 = *(const float4*)(wr);
            wa1 = *(const float4*)(wr + 4);
            const float* xr = ab + (size_t)(k0 + brow) * NTOK + i0 + bi;
            xa0 = *(const float4*)(xr);
            xa1 = *(const float4*)(xr + 4);
        }
        uint32_t ah[4][4], al[4][4];
        #pragma unroll
        for (int mt = 0; mt < 4; mt++) {
            int r = wm + mt * 16 + (lm & 1) * 8 + lr;
            ldsm_x4(ah[mt], smem_u32(&Ash[buf][r][(lm >> 1) * 8]));
            ldsm_x4(al[mt], smem_u32(&Asl[buf][r][(lm >> 1) * 8]));
        }
        uint32_t bh[2][4], bl[2][4];
        #pragma unroll
        for (int np = 0; np < 2; np++) {
            int r = (lm & 1) * 8 + lr;
            int c = wn + np * 16 + (lm >> 1) * 8;
            ldsm_x4_t(bh[np], smem_u32(&Bsh[buf][r][c]));
            ldsm_x4_t(bl[np], smem_u32(&Bsl[buf][r][c]));
        }
        #pragma unroll
        for (int mt = 0; mt < 4; mt++)
            #pragma unroll
            for (int nt = 0; nt < 4; nt++) {
                int np = nt >> 1, pp = (nt & 1) * 2;
                MMA_BF16(acc[mt][nt], ah[mt], bh[np][pp], bh[np][pp + 1]);
                MMA_BF16(acc[mt][nt], al[mt], bh[np][pp], bh[np][pp + 1]);
                MMA_BF16(acc[mt][nt], ah[mt], bl[np][pp], bl[np][pp + 1]);
            }
        if (kt < 7) {
            split8_store(&Ash[buf ^ 1][arow][ac], &Asl[buf ^ 1][arow][ac], wa0, wa1);
            split8_store(&Bsh[buf ^ 1][brow][bi], &Bsl[buf ^ 1][brow][bi], xa0, xa1);
        }
        __syncthreads();
    }

    #pragma unroll
    for (int mt = 0; mt < 4; mt++) {
        #pragma unroll
        for (int rr = 0; rr < 2; rr++) {
            int o = obase + wm + mt * 16 + (lane >> 2) + rr * 8;
            float bias = __ldg(&b_out[o]);
            float* yr = y + ((size_t)b * CDIM + o) * NTOK;
            #pragma unroll
            for (int nt = 0; nt < 4; nt++) {
                int i = i0 + wn + nt * 8 + (lane & 3) * 2;
                float2 v;
                v.x = acc[mt][nt][rr * 2]     + bias;
                v.y = acc[mt][nt][rr * 2 + 1] + bias;
                *(float2*)&yr[i] = v;
            }
        }
    }
}

// ---------------- launch ----------------
extern "C" void kernel_launch(void* const* d_in, const int* in_sizes, int n_in,
                              void* d_out, int out_size) {
    const float* x     = (const float*)d_in[0];
    const float* gamma = (const float*)d_in[1];
    const float* beta  = (const float*)d_in[2];
    const float* w_qkv = (const float*)d_in[3];
    const float* w_out = (const float*)d_in[4];
    const float* b_out = (const float*)d_in[5];
    float* y = (float*)d_out;

    k_reduce1<<<dim3(64, BATCH), 256>>>(x);
    k_reduce2<<<1, 256>>>();
    k_qkv_mma<<<dim3(NTOK / 128, 3, BATCH), 256>>>(x, gamma, beta, w_qkv);
    k_attn_mma<<<dim3(NTOK / 128, BATCH * HEADS), 128>>>();
    k_out_mma<<<dim3(NTOK / 128, CDIM / 128, BATCH), 256>>>(y, w_out, b_out);
}

// round 13
// speedup vs baseline: 1.6597x; 1.6597x over previous
#include <cuda_runtime.h>
#include <cuda_bf16.h>
#include <cuda_fp16.h>
#include <math_constants.h>
#include <cstdint>

// Problem constants
#define BATCH 4
#define CDIM 256
#define NTOK 4096          // 64*64
#define HEADS 4
#define DH 32
#define HID 128            // HEADS*DH
#define OQKV 384           // 3*HID
#define NPB 1048576        // CDIM*NTOK per batch
#define SCALE_LOG2E 0.25494291280534f  // 32^-0.5 * log2(e)
#define KSPLIT 2
#define KHALF (NTOK / KSPLIT)          // 2048 keys per split
#define AOSZ ((size_t)BATCH * HID * NTOK)
#define LSZ  ((size_t)BATCH * HEADS * NTOK)

// ---------------- device scratch ----------------
__device__ float g_psum[BATCH * 64];
__device__ float g_psq [BATCH * 64];
__device__ float g_mu[BATCH];
__device__ float g_rs[BATCH];
__device__ __half g_qh[BATCH * HEADS * NTOK * DH];   // pre-scaled by SCALE*log2e
__device__ __half g_kh[BATCH * HEADS * NTOK * DH];
__device__ __half g_vh[BATCH * HEADS * NTOK * DH];
__device__ float g_aop[KSPLIT * BATCH * HID * NTOK];   // unnormalized partial O, [half][b][c][i]
__device__ float g_lp [KSPLIT * BATCH * HEADS * NTOK]; // partial softmax denominators

__device__ __forceinline__ uint32_t smem_u32(const void* p) {
    uint32_t a;
    asm("{ .reg .u64 t; cvta.to.shared.u64 t, %1; cvt.u32.u64 %0, t; }" : "=r"(a) : "l"(p));
    return a;
}
__device__ __forceinline__ void ldsm_x4(uint32_t* r, uint32_t a) {
    asm volatile("ldmatrix.sync.aligned.m8n8.x4.shared.b16 {%0,%1,%2,%3}, [%4];"
                 : "=r"(r[0]), "=r"(r[1]), "=r"(r[2]), "=r"(r[3]) : "r"(a));
}
__device__ __forceinline__ void ldsm_x4_t(uint32_t* r, uint32_t a) {
    asm volatile("ldmatrix.sync.aligned.m8n8.x4.trans.shared.b16 {%0,%1,%2,%3}, [%4];"
                 : "=r"(r[0]), "=r"(r[1]), "=r"(r[2]), "=r"(r[3]) : "r"(a));
}
#define MMA_BF16(d, a, b0_, b1_) \
    asm volatile("mma.sync.aligned.m16n8k16.row.col.f32.bf16.bf16.f32 " \
                 "{%0,%1,%2,%3}, {%4,%5,%6,%7}, {%8,%9}, {%0,%1,%2,%3};" \
                 : "+f"((d)[0]), "+f"((d)[1]), "+f"((d)[2]), "+f"((d)[3]) \
                 : "r"((a)[0]), "r"((a)[1]), "r"((a)[2]), "r"((a)[3]), "r"(b0_), "r"(b1_))
#define MMA_F16(d, a, b0_, b1_) \
    asm volatile("mma.sync.aligned.m16n8k16.row.col.f32.f16.f16.f32 " \
                 "{%0,%1,%2,%3}, {%4,%5,%6,%7}, {%8,%9}, {%0,%1,%2,%3};" \
                 : "+f"((d)[0]), "+f"((d)[1]), "+f"((d)[2]), "+f"((d)[3]) \
                 : "r"((a)[0]), "r"((a)[1]), "r"((a)[2]), "r"((a)[3]), "r"(b0_), "r"(b1_))
#define PACK_BF16X2(r, lo, hi) \
    asm("cvt.rn.bf16x2.f32 %0, %1, %2;" : "=r"(r) : "f"(hi), "f"(lo))
#define PACK_F16X2(r, lo, hi) \
    asm("cvt.rn.f16x2.f32 %0, %1, %2;" : "=r"(r) : "f"(hi), "f"(lo))
#define EX2_F16X2(r, a) \
    asm("ex2.approx.f16x2 %0, %1;" : "=r"(r) : "r"(a))
#define ONES_F16X2 0x3C003C00u

// exact truncation split: f = hi(bf16, trunc) + lo residual (for fp32-accurate GEMM)
__device__ __forceinline__ void split_pack2(uint32_t& h, uint32_t& l, float a, float b) {
    uint32_t ua = __float_as_uint(a), ub = __float_as_uint(b);
    h = (ua >> 16) | (ub & 0xffff0000u);
    float la = a - __uint_as_float(ua & 0xffff0000u);
    float lb = b - __uint_as_float(ub & 0xffff0000u);
    PACK_BF16X2(l, la, lb);
}
__device__ __forceinline__ void split8_store(__nv_bfloat16* dh, __nv_bfloat16* dl,
                                             float4 a, float4 b) {
    uint4 H, L;
    split_pack2(H.x, L.x, a.x, a.y);
    split_pack2(H.y, L.y, a.z, a.w);
    split_pack2(H.z, L.z, b.x, b.y);
    split_pack2(H.w, L.w, b.z, b.w);
    *(uint4*)dh = H;
    *(uint4*)dl = L;
}

// combine split-K partials: (o0+o1) / (l0+l1) for 8 consecutive tokens
__device__ __forceinline__ void load_ao8(int b, int c, int ibase, float4& x0, float4& x1) {
    const float* p0 = g_aop + (size_t)b * HID * NTOK + (size_t)c * NTOK + ibase;
    const float* p1 = p0 + AOSZ;
    int head = c >> 5;
    const float* l0 = g_lp + ((size_t)b * HEADS + head) * NTOK + ibase;
    const float* l1 = l0 + LSZ;
    float4 A0 = *(const float4*)p0,       A1 = *(const float4*)(p0 + 4);
    float4 B0 = *(const float4*)p1,       B1 = *(const float4*)(p1 + 4);
    float4 L0 = *(const float4*)l0,       L1 = *(const float4*)(l0 + 4);
    float4 M0 = *(const float4*)l1,       M1 = *(const float4*)(l1 + 4);
    x0.x = __fdividef(A0.x + B0.x, L0.x + M0.x);
    x0.y = __fdividef(A0.y + B0.y, L0.y + M0.y);
    x0.z = __fdividef(A0.z + B0.z, L0.z + M0.z);
    x0.w = __fdividef(A0.w + B0.w, L0.w + M0.w);
    x1.x = __fdividef(A1.x + B1.x, L1.x + M1.x);
    x1.y = __fdividef(A1.y + B1.y, L1.y + M1.y);
    x1.z = __fdividef(A1.z + B1.z, L1.z + M1.z);
    x1.w = __fdividef(A1.w + B1.w, L1.w + M1.w);
}

// ---------------- kernel 1: per-batch sum / sumsq partials ----------------
__global__ void k_reduce1(const float* __restrict__ x) {
    int b = blockIdx.y;
    int blk = blockIdx.x;
    int tid = threadIdx.x;
    const float4* xb = (const float4*)(x + (size_t)b * NPB);
    float s = 0.f, sq = 0.f;
    int base = blk * 4096 + tid;
    #pragma unroll
    for (int t = 0; t < 16; t++) {
        float4 v = xb[base + t * 256];
        s  += (v.x + v.y) + (v.z + v.w);
        sq += (v.x * v.x + v.y * v.y) + (v.z * v.z + v.w * v.w);
    }
    __shared__ float ss[256], sg[256];
    ss[tid] = s; sg[tid] = sq;
    __syncthreads();
    for (int off = 128; off >= 1; off >>= 1) {
        if (tid < off) { ss[tid] += ss[tid + off]; sg[tid] += sg[tid + off]; }
        __syncthreads();
    }
    if (tid == 0) { g_psum[b * 64 + blk] = ss[0]; g_psq[b * 64 + blk] = sg[0]; }
}

// ---------------- kernel 2: finalize mean / rsigma ----------------
__global__ void k_reduce2() {
    int tid = threadIdx.x;
    int b = tid / 64, j = tid % 64;
    __shared__ float ss[256], sg[256];
    ss[tid] = g_psum[tid]; sg[tid] = g_psq[tid];
    __syncthreads();
    for (int off = 32; off >= 1; off >>= 1) {
        if (j < off) { ss[tid] += ss[tid + off]; sg[tid] += sg[tid + off]; }
        __syncthreads();
    }
    if (j == 0) {
        float mu = ss[tid] * (1.f / (float)NPB);
        float var = sg[tid] * (1.f / (float)NPB) - mu * mu;
        g_mu[b] = mu;
        g_rs[b] = rsqrtf(var + 1e-5f);
    }
}

// ---------------- kernel 3: LN + QKV GEMM (split-bf16 tensor cores) --------
__global__ void __launch_bounds__(256) k_qkv_mma(const float* __restrict__ x,
                                                 const float* __restrict__ gamma,
                                                 const float* __restrict__ beta,
                                                 const float* __restrict__ wqkv) {
    __shared__ __align__(16) __nv_bfloat16 Ash[2][128][24];
    __shared__ __align__(16) __nv_bfloat16 Asl[2][128][24];
    __shared__ __align__(16) __nv_bfloat16 Bsh[2][16][136];
    __shared__ __align__(16) __nv_bfloat16 Bsl[2][16][136];

    int b = blockIdx.z;
    int i0 = blockIdx.x * 128;
    int which = blockIdx.y;            // 0=q, 1=k, 2=v
    int obase = which * 128;
    int tid = threadIdx.x;
    int wid = tid >> 5, lane = tid & 31;
    int wm = (wid >> 2) * 64;
    int wn = (wid & 3) * 32;
    int lr = lane & 7, lm = lane >> 3;

    float mu = g_mu[b], rs = g_rs[b];
    const float* xb = x + (size_t)b * NPB;

    int arow = tid >> 1, ac = (tid & 1) * 8;
    int brow = tid >> 4, bi = (tid & 15) * 8;

    float4 wa0, wa1, xa0, xa1;
    {
        const float* wr = wqkv + (size_t)(obase + arow) * CDIM + ac;
        wa0 = *(const float4*)(wr);
        wa1 = *(const float4*)(wr + 4);
        const float* xr = xb + (size_t)brow * NTOK + i0 + bi;
        xa0 = *(const float4*)(xr);
        xa1 = *(const float4*)(xr + 4);
    }
    {
        split8_store(&Ash[0][arow][ac], &Asl[0][arow][ac], wa0, wa1);
        float a = rs * __ldg(&gamma[brow]);
        float bb = __ldg(&beta[brow]) - mu * a;
        float4 t0 = make_float4(xa0.x*a+bb, xa0.y*a+bb, xa0.z*a+bb, xa0.w*a+bb);
        float4 t1 = make_float4(xa1.x*a+bb, xa1.y*a+bb, xa1.z*a+bb, xa1.w*a+bb);
        split8_store(&Bsh[0][brow][bi], &Bsl[0][brow][bi], t0, t1);
    }
    __syncthreads();

    float acc[4][4][4] = {};
    #pragma unroll 1
    for (int kt = 0; kt < 16; kt++) {
        int buf = kt & 1;
        if (kt < 15) {
            int k0 = (kt + 1) * 16;
            const float* wr = wqkv + (size_t)(obase + arow) * CDIM + k0 + ac;
            wa0 = *(const float4*)(wr);
            wa1 = *(const float4*)(wr + 4);
            const float* xr = xb + (size_t)(k0 + brow) * NTOK + i0 + bi;
            xa0 = *(const float4*)(xr);
            xa1 = *(const float4*)(xr + 4);
        }
        uint32_t ah[4][4], al[4][4];
        #pragma unroll
        for (int mt = 0; mt < 4; mt++) {
            int r = wm + mt * 16 + (lm & 1) * 8 + lr;
            ldsm_x4(ah[mt], smem_u32(&Ash[buf][r][(lm >> 1) * 8]));
            ldsm_x4(al[mt], smem_u32(&Asl[buf][r][(lm >> 1) * 8]));
        }
        uint32_t bh[2][4], bl[2][4];
        #pragma unroll
        for (int np = 0; np < 2; np++) {
            int r = (lm & 1) * 8 + lr;
            int c = wn + np * 16 + (lm >> 1) * 8;
            ldsm_x4_t(bh[np], smem_u32(&Bsh[buf][r][c]));
            ldsm_x4_t(bl[np], smem_u32(&Bsl[buf][r][c]));
        }
        #pragma unroll
        for (int mt = 0; mt < 4; mt++)
            #pragma unroll
            for (int nt = 0; nt < 4; nt++) {
                int np = nt >> 1, pp = (nt & 1) * 2;
                MMA_BF16(acc[mt][nt], ah[mt], bh[np][pp], bh[np][pp + 1]);
                MMA_BF16(acc[mt][nt], al[mt], bh[np][pp], bh[np][pp + 1]);
                MMA_BF16(acc[mt][nt], ah[mt], bl[np][pp], bl[np][pp + 1]);
            }
        if (kt < 15) {
            int k0 = (kt + 1) * 16;
            split8_store(&Ash[buf ^ 1][arow][ac], &Asl[buf ^ 1][arow][ac], wa0, wa1);
            int c = k0 + brow;
            float a = rs * __ldg(&gamma[c]);
            float bb = __ldg(&beta[c]) - mu * a;
            float4 t0 = make_float4(xa0.x*a+bb, xa0.y*a+bb, xa0.z*a+bb, xa0.w*a+bb);
            float4 t1 = make_float4(xa1.x*a+bb, xa1.y*a+bb, xa1.z*a+bb, xa1.w*a+bb);
            split8_store(&Bsh[buf ^ 1][brow][bi], &Bsl[buf ^ 1][brow][bi], t0, t1);
        }
        __syncthreads();
    }

    // epilogue: scatter to q / k / v (fp16)
    #pragma unroll
    for (int mt = 0; mt < 4; mt++) {
        #pragma unroll
        for (int rr = 0; rr < 2; rr++) {
            int ol = wm + mt * 16 + (lane >> 2) + rr * 8;
            int head = ol >> 5, d = ol & 31;
            size_t base = ((size_t)(b * HEADS + head) * NTOK) * DH + d;
            #pragma unroll
            for (int nt = 0; nt < 4; nt++) {
                int i = i0 + wn + nt * 8 + (lane & 3) * 2;
                float v0 = acc[mt][nt][rr * 2];
                float v1 = acc[mt][nt][rr * 2 + 1];
                size_t idx0 = base + (size_t)i * DH;
                size_t idx1 = base + (size_t)(i + 1) * DH;
                if (which == 0) {
                    g_qh[idx0] = __float2half_rn(v0 * SCALE_LOG2E);
                    g_qh[idx1] = __float2half_rn(v1 * SCALE_LOG2E);
                } else if (which == 1) {
                    g_kh[idx0] = __float2half_rn(v0);
                    g_kh[idx1] = __float2half_rn(v1);
                } else {
                    g_vh[idx0] = __float2half_rn(v0);
                    g_vh[idx1] = __float2half_rn(v1);
                }
            }
        }
    }
}

// ---------------- kernel 4: flash attention, split-K over 2 key-halves ------
// 128 threads / 4 warps, 32 q-rows per warp (round-11 body unchanged).
// grid: (32 q-tiles, 16 bh, 2 key-halves). Each CTA covers 2048 keys and
// writes UNNORMALIZED partial O + partial denominator l (additive combine,
// valid because there is no online max). Q staged through K-buffer overlay.
__global__ void __launch_bounds__(128, 3) k_attn_mma() {
    __shared__ __align__(16) __half Ks[2][64][40];
    __shared__ __align__(16) __half Vs[2][64][40];

    int tid = threadIdx.x;
    int wid = tid >> 5, lane = tid & 31;
    int bh = blockIdx.y;
    int i0 = blockIdx.x * 128;
    int half = blockIdx.z;
    int wrow = wid * 32;

    const __half* kb = g_kh + (size_t)bh * NTOK * DH + (size_t)half * KHALF * DH;
    const __half* vb = g_vh + (size_t)bh * NTOK * DH + (size_t)half * KHALF * DH;
    const __half* qg = g_qh + (size_t)bh * NTOK * DH;

    // stage Q (128 x 32 fp16 = 10KB) over the whole Ks region
    __half (*Qs)[40] = &Ks[0][0];
    {
        int qr = tid;
        const __half* src = qg + (size_t)(i0 + qr) * DH;
        *(uint4*)&Qs[qr][0]  = *(const uint4*)(src);
        *(uint4*)&Qs[qr][8]  = *(const uint4*)(src + 8);
        *(uint4*)&Qs[qr][16] = *(const uint4*)(src + 16);
        *(uint4*)&Qs[qr][24] = *(const uint4*)(src + 24);
    }
    __syncthreads();

    int lr = lane & 7, lm = lane >> 3;

    uint32_t qf[2][2][4];
    #pragma unroll
    for (int mt = 0; mt < 2; mt++)
        #pragma unroll
        for (int ks = 0; ks < 2; ks++)
            ldsm_x4(qf[mt][ks],
                    smem_u32(&Qs[wrow + mt * 16 + (lm & 1) * 8 + lr][ks * 16 + (lm >> 1) * 8]));
    __syncthreads();   // done reading Q before K tile 0 overwrites

    float o[2][4][4] = {};
    float lacc[2][4] = {};

    int c0 = tid, c1 = tid + 128;
    int r0 = c0 >> 2, ch0 = (c0 & 3) * 8;
    int r1 = c1 >> 2, ch1 = (c1 & 3) * 8;

    uint4 kp0 = *(const uint4*)(kb + (size_t)r0 * DH + ch0);
    uint4 kp1 = *(const uint4*)(kb + (size_t)r1 * DH + ch1);
    uint4 vp0 = *(const uint4*)(vb + (size_t)r0 * DH + ch0);
    uint4 vp1 = *(const uint4*)(vb + (size_t)r1 * DH + ch1);
    *(uint4*)&Ks[0][r0][ch0] = kp0;
    *(uint4*)&Ks[0][r1][ch1] = kp1;
    *(uint4*)&Vs[0][r0][ch0] = vp0;
    *(uint4*)&Vs[0][r1][ch1] = vp1;
    __syncthreads();

    #pragma unroll 1
    for (int t = 0; t < KHALF / 64; t++) {
        int buf = t & 1;
        if (t < KHALF / 64 - 1) {
            size_t j0 = (size_t)(t + 1) * 64;
            kp0 = *(const uint4*)(kb + (j0 + r0) * DH + ch0);
            kp1 = *(const uint4*)(kb + (j0 + r1) * DH + ch1);
            vp0 = *(const uint4*)(vb + (j0 + r0) * DH + ch0);
            vp1 = *(const uint4*)(vb + (j0 + r1) * DH + ch1);
        }

        // ---- S = Q @ K^T : per warp 32 x 64 ----
        float s[2][8][4] = {};
        #pragma unroll
        for (int ks = 0; ks < 2; ks++) {
            #pragma unroll
            for (int ntp = 0; ntp < 4; ntp++) {
                uint32_t kf[4];
                ldsm_x4(kf, smem_u32(&Ks[buf][ntp * 16 + (lm >> 1) * 8 + lr][ks * 16 + (lm & 1) * 8]));
                #pragma unroll
                for (int mt = 0; mt < 2; mt++) {
                    MMA_F16(s[mt][2 * ntp],     qf[mt][ks], kf[0], kf[1]);
                    MMA_F16(s[mt][2 * ntp + 1], qf[mt][ks], kf[2], kf[3]);
                }
            }
        }

        // ---- per 16 keys: pack s, p = ex2.f16x2, PV + ones MMA ----
        #pragma unroll
        for (int kk = 0; kk < 4; kk++) {
            uint32_t vf[2][4];
            #pragma unroll
            for (int dp = 0; dp < 2; dp++)
                ldsm_x4_t(vf[dp],
                          smem_u32(&Vs[buf][kk * 16 + (lm & 1) * 8 + lr][dp * 16 + (lm >> 1) * 8]));
            #pragma unroll
            for (int mt = 0; mt < 2; mt++) {
                uint32_t sf[4], af[4];
                PACK_F16X2(sf[0], s[mt][2 * kk][0],     s[mt][2 * kk][1]);
                PACK_F16X2(sf[1], s[mt][2 * kk][2],     s[mt][2 * kk][3]);
                PACK_F16X2(sf[2], s[mt][2 * kk + 1][0], s[mt][2 * kk + 1][1]);
                PACK_F16X2(sf[3], s[mt][2 * kk + 1][2], s[mt][2 * kk + 1][3]);
                EX2_F16X2(af[0], sf[0]);
                EX2_F16X2(af[1], sf[1]);
                EX2_F16X2(af[2], sf[2]);
                EX2_F16X2(af[3], sf[3]);
                MMA_F16(o[mt][0], af, vf[0][0], vf[0][1]);
                MMA_F16(o[mt][1], af, vf[0][2], vf[0][3]);
                MMA_F16(o[mt][2], af, vf[1][0], vf[1][1]);
                MMA_F16(o[mt][3], af, vf[1][2], vf[1][3]);
                MMA_F16(lacc[mt], af, ONES_F16X2, ONES_F16X2);
            }
        }

        if (t < KHALF / 64 - 1) {
            *(uint4*)&Ks[buf ^ 1][r0][ch0] = kp0;
            *(uint4*)&Ks[buf ^ 1][r1][ch1] = kp1;
            *(uint4*)&Vs[buf ^ 1][r0][ch0] = vp0;
            *(uint4*)&Vs[buf ^ 1][r1][ch1] = vp1;
        }
        __syncthreads();
    }

    // ---- epilogue: write UNNORMALIZED partials ----
    int b = bh >> 2, hd = bh & 3;
    float* dst = g_aop + (size_t)half * AOSZ + ((size_t)b * HID + hd * DH) * NTOK;
    float* lp  = g_lp  + (size_t)half * LSZ + (size_t)bh * NTOK;
    int cbase = (lane & 3) * 2;
    #pragma unroll
    for (int mt = 0; mt < 2; mt++) {
        int rbase = i0 + wrow + mt * 16 + (lane >> 2);
        #pragma unroll
        for (int h = 0; h < 2; h++) {
            int i = rbase + h * 8;
            if ((lane & 3) == 0) lp[i] = lacc[mt][h * 2];
            #pragma unroll
            for (int dd = 0; dd < 4; dd++) {
                int d = dd * 8 + cbase;
                dst[(size_t)d * NTOK + i]       = o[mt][dd][h * 2];
                dst[(size_t)(d + 1) * NTOK + i] = o[mt][dd][h * 2 + 1];
            }
        }
    }
}

// ---------------- kernel 5: output GEMM + bias ------------------------------
// B operand = (o0+o1)/(l0+l1) combined on the fly during staging.
__global__ void __launch_bounds__(256) k_out_mma(float* __restrict__ y,
                                                 const float* __restrict__ wout,
                                                 const float* __restrict__ b_out) {
    __shared__ __align__(16) __nv_bfloat16 Ash[2][128][24];
    __shared__ __align__(16) __nv_bfloat16 Asl[2][128][24];
    __shared__ __align__(16) __nv_bfloat16 Bsh[2][16][136];
    __shared__ __align__(16) __nv_bfloat16 Bsl[2][16][136];

    int b = blockIdx.z;
    int i0 = blockIdx.x * 128;
    int obase = blockIdx.y * 128;
    int tid = threadIdx.x;
    int wid = tid >> 5, lane = tid & 31;
    int wm = (wid >> 2) * 64;
    int wn = (wid & 3) * 32;
    int lr = lane & 7, lm = lane >> 3;

    int arow = tid >> 1, ac = (tid & 1) * 8;
    int brow = tid >> 4, bi = (tid & 15) * 8;

    float4 wa0, wa1, xa0, xa1;
    {
        const float* wr = wout + (size_t)(obase + arow) * HID + ac;
        wa0 = *(const float4*)(wr);
        wa1 = *(const float4*)(wr + 4);
        load_ao8(b, brow, i0 + bi, xa0, xa1);
    }
    split8_store(&Ash[0][arow][ac], &Asl[0][arow][ac], wa0, wa1);
    split8_store(&Bsh[0][brow][bi], &Bsl[0][brow][bi], xa0, xa1);
    __syncthreads();

    float acc[4][4][4] = {};
    #pragma unroll 1
    for (int kt = 0; kt < 8; kt++) {
        int buf = kt & 1;
        if (kt < 7) {
            int k0 = (kt + 1) * 16;
            const float* wr = wout + (size_t)(obase + arow) * HID + k0 + ac;
            wa0 = *(const float4*)(wr);
            wa1 = *(const float4*)(wr + 4);
            load_ao8(b, k0 + brow, i0 + bi, xa0, xa1);
        }
        uint32_t ah[4][4], al[4][4];
        #pragma unroll
        for (int mt = 0; mt < 4; mt++) {
            int r = wm + mt * 16 + (lm & 1) * 8 + lr;
            ldsm_x4(ah[mt], smem_u32(&Ash[buf][r][(lm >> 1) * 8]));
            ldsm_x4(al[mt], smem_u32(&Asl[buf][r][(lm >> 1) * 8]));
        }
        uint32_t bh[2][4], bl[2][4];
        #pragma unroll
        for (int np = 0; np < 2; np++) {
            int r = (lm & 1) * 8 + lr;
            int c = wn + np * 16 + (lm >> 1) * 8;
            ldsm_x4_t(bh[np], smem_u32(&Bsh[buf][r][c]));
            ldsm_x4_t(bl[np], smem_u32(&Bsl[buf][r][c]));
        }
        #pragma unroll
        for (int mt = 0; mt < 4; mt++)
            #pragma unroll
            for (int nt = 0; nt < 4; nt++) {
                int np = nt >> 1, pp = (nt & 1) * 2;
                MMA_BF16(acc[mt][nt], ah[mt], bh[np][pp], bh[np][pp + 1]);
                MMA_BF16(acc[mt][nt], al[mt], bh[np][pp], bh[np][pp + 1]);
                MMA_BF16(acc[mt][nt], ah[mt], bl[np][pp], bl[np][pp + 1]);
            }
        if (kt < 7) {
            split8_store(&Ash[buf ^ 1][arow][ac], &Asl[buf ^ 1][arow][ac], wa0, wa1);
            split8_store(&Bsh[buf ^ 1][brow][bi], &Bsl[buf ^ 1][brow][bi], xa0, xa1);
        }
        __syncthreads();
    }

    #pragma unroll
    for (int mt = 0; mt < 4; mt++) {
        #pragma unroll
        for (int rr = 0; rr < 2; rr++) {
            int o = obase + wm + mt * 16 + (lane >> 2) + rr * 8;
            float bias = __ldg(&b_out[o]);
            float* yr = y + ((size_t)b * CDIM + o) * NTOK;
            #pragma unroll
            for (int nt = 0; nt < 4; nt++) {
                int i = i0 + wn + nt * 8 + (lane & 3) * 2;
                float2 v;
                v.x = acc[mt][nt][rr * 2]     + bias;
                v.y = acc[mt][nt][rr * 2 + 1] + bias;
                *(float2*)&yr[i] = v;
            }
        }
    }
}

// ---------------- launch ----------------
extern "C" void kernel_launch(void* const* d_in, const int* in_sizes, int n_in,
                              void* d_out, int out_size) {
    const float* x     = (const float*)d_in[0];
    const float* gamma = (const float*)d_in[1];
    const float* beta  = (const float*)d_in[2];
    const float* w_qkv = (const float*)d_in[3];
    const float* w_out = (const float*)d_in[4];
    const float* b_out = (const float*)d_in[5];
    float* y = (float*)d_out;

    k_reduce1<<<dim3(64, BATCH), 256>>>(x);
    k_reduce2<<<1, 256>>>();
    k_qkv_mma<<<dim3(NTOK / 128, 3, BATCH), 256>>>(x, gamma, beta, w_qkv);
    k_attn_mma<<<dim3(NTOK / 128, BATCH * HEADS, KSPLIT), 128>>>();
    k_out_mma<<<dim3(NTOK / 128, CDIM / 128, BATCH), 256>>>(y, w_out, b_out);
}